// round 3
// baseline (speedup 1.0000x reference)
#include <cuda_runtime.h>
#include <math.h>

#define B_   32
#define T_   128
#define H_   256
#define V_   32000
#define BT_  (B_*T_)
#define PROBS_ ((size_t)BT_ * V_)

// ---------------- device scratch (no allocation allowed) ----------------
__device__ float g_x[BT_*H_];      // embedded+masked input
__device__ float g_pre[BT_*H_];    // x@Wx^T + b  (reused per layer)
__device__ float g_h1[BT_*H_];     // layer-1 masked output
__device__ float g_WxT[H_*H_];     // transposed Wx (current layer)
__device__ float g_WhT[H_*H_];     // transposed Wh (current layer)
__device__ float g_rowsum[BT_];    // softmax denominators -> inverses

// ---------------- small utility kernels ----------------
__global__ void zero_rowsum_kernel(float* rs) {
    int i = blockIdx.x * 256 + threadIdx.x;
    if (i < BT_) rs[i] = 0.f;
}

__global__ void embed_kernel(const int* __restrict__ tokens,
                             const int* __restrict__ lengths,
                             const float* __restrict__ emb,
                             float* __restrict__ x) {
    int i = blockIdx.x;            // (b,t) row 0..4095
    int j = threadIdx.x;           // 0..255
    int b = i >> 7, t = i & (T_-1);
    int tok = tokens[i];
    float v = (t < lengths[b]) ? emb[(size_t)tok * H_ + j] : 0.f;
    x[(size_t)i * H_ + j] = v;
}

// dst[k][j] = src[j][k], 256x256
__global__ void transpose_kernel(const float* __restrict__ src,
                                 float* __restrict__ dst) {
    __shared__ float tile[32][33];
    int x = blockIdx.x * 32 + threadIdx.x;
    int y = blockIdx.y * 32 + threadIdx.y;
    tile[threadIdx.y][threadIdx.x] = src[y * H_ + x];
    __syncthreads();
    x = blockIdx.y * 32 + threadIdx.x;
    y = blockIdx.x * 32 + threadIdx.y;
    dst[y * H_ + x] = tile[threadIdx.x][threadIdx.y];
}

// ---------------- pre-activation GEMM: out[i][j] = b[j] + sum_k X[i][k]*W[j][k]
// WT is W transposed: WT[k][j]. 16 rows of X per CTA, 256 threads (one j each).
__global__ __launch_bounds__(256)
void pre_gemm_kernel(const float* __restrict__ X,
                     const float* __restrict__ WT,
                     const float* __restrict__ bias,
                     float* __restrict__ out) {
    __shared__ float Xs[H_][16];           // [k][m]
    const int r0 = blockIdx.x * 16;
    const int tid = threadIdx.x;
    {
        int m  = tid >> 4;                 // 0..15
        int kq = (tid & 15) * 16;          // 0..240
        const float4* src = reinterpret_cast<const float4*>(&X[(size_t)(r0+m)*H_ + kq]);
        #pragma unroll
        for (int i = 0; i < 4; ++i) {
            float4 v = src[i];
            int k = kq + i * 4;
            Xs[k+0][m] = v.x; Xs[k+1][m] = v.y; Xs[k+2][m] = v.z; Xs[k+3][m] = v.w;
        }
    }
    __syncthreads();
    const int j = tid;
    float bb = bias[j];
    float acc[16];
    #pragma unroll
    for (int m = 0; m < 16; ++m) acc[m] = bb;
    #pragma unroll 8
    for (int k = 0; k < H_; ++k) {
        float w = WT[k * H_ + j];
        #pragma unroll
        for (int m0 = 0; m0 < 16; m0 += 4) {
            float4 xv = *reinterpret_cast<const float4*>(&Xs[k][m0]);
            acc[m0+0] = fmaf(w, xv.x, acc[m0+0]);
            acc[m0+1] = fmaf(w, xv.y, acc[m0+1]);
            acc[m0+2] = fmaf(w, xv.z, acc[m0+2]);
            acc[m0+3] = fmaf(w, xv.w, acc[m0+3]);
        }
    }
    #pragma unroll
    for (int m = 0; m < 16; ++m) out[(size_t)(r0+m)*H_ + j] = acc[m];
}

// ---------------- recurrence: one CTA per batch element, h lives in SMEM.
// h_new[j] = tanh(pre[t][j] + sum_k WhT[k][j]*h[k]); output masked, state unmasked.
__global__ __launch_bounds__(256)
void rnn_kernel(const float* __restrict__ pre,
                const float* __restrict__ WhT,
                const int* __restrict__ lengths,
                float* __restrict__ hout) {
    __shared__ float hs[H_];
    __shared__ float red[3][H_];
    const int b   = blockIdx.x;
    const int tid = threadIdx.x;
    const int jj  = (tid & 63) * 4;      // output quad
    const int kk  = tid >> 6;            // k-slice 0..3
    const int k0  = kk * 64;
    hs[tid] = 0.f;
    __syncthreads();
    const int len = lengths[b];
    const float* preb = pre  + (size_t)b * T_ * H_;
    float*      houtb = hout + (size_t)b * T_ * H_;

    for (int t = 0; t < T_; ++t) {
        float a0 = 0.f, a1 = 0.f, a2 = 0.f, a3 = 0.f;
        const float* wp = WhT + (size_t)k0 * H_ + jj;
        #pragma unroll 16
        for (int k = 0; k < 64; ++k) {
            float h = hs[k0 + k];
            float4 w = *reinterpret_cast<const float4*>(wp);
            wp += H_;
            a0 = fmaf(w.x, h, a0); a1 = fmaf(w.y, h, a1);
            a2 = fmaf(w.z, h, a2); a3 = fmaf(w.w, h, a3);
        }
        if (kk > 0)
            *reinterpret_cast<float4*>(&red[kk-1][jj]) = make_float4(a0, a1, a2, a3);
        __syncthreads();
        if (kk == 0) {
            #pragma unroll
            for (int r = 0; r < 3; ++r) {
                float4 rv = *reinterpret_cast<const float4*>(&red[r][jj]);
                a0 += rv.x; a1 += rv.y; a2 += rv.z; a3 += rv.w;
            }
            float4 p = *reinterpret_cast<const float4*>(&preb[t * H_ + jj]);
            float h0 = tanhf(a0 + p.x), h1 = tanhf(a1 + p.y);
            float h2 = tanhf(a2 + p.z), h3 = tanhf(a3 + p.w);
            hs[jj+0] = h0; hs[jj+1] = h1; hs[jj+2] = h2; hs[jj+3] = h3;
            float m = (t < len) ? 1.f : 0.f;
            *reinterpret_cast<float4*>(&houtb[t * H_ + jj]) =
                make_float4(h0*m, h1*m, h2*m, h3*m);
        }
        __syncthreads();
    }
}

// ---------------- tied projection GEMM + exp + row-sum ----------------
// out[m][n] = exp(sum_k A[m][k]*Bmat[n][k]); rowsum[m] += partials.
#define PBM 128
#define PBN 128
#define PBK 32
__global__ __launch_bounds__(256, 2)
void proj_kernel(const float* __restrict__ A,       // h2 [4096][256]
                 const float* __restrict__ Bmat,    // emb [32000][256]
                 float* __restrict__ out,           // [4096][32000]
                 float* __restrict__ rowsum) {
    __shared__ float As[PBK][PBM];
    __shared__ float Bs[PBK][PBN];
    const int gm  = blockIdx.y * PBM;
    const int gn  = blockIdx.x * PBN;
    const int tid = threadIdx.x;
    const int tx  = tid & 15;
    const int ty  = tid >> 4;
    const int m0  = ty * 8;
    const int n0  = tx * 8;
    const int lr  = tid >> 1;          // 0..127
    const int lk  = (tid & 1) * 16;    // 0 or 16

    float acc[8][8];
    #pragma unroll
    for (int i = 0; i < 8; ++i)
        #pragma unroll
        for (int j = 0; j < 8; ++j) acc[i][j] = 0.f;

    for (int k0 = 0; k0 < H_; k0 += PBK) {
        const float4* sa = reinterpret_cast<const float4*>(&A   [(size_t)(gm+lr)*H_ + k0 + lk]);
        const float4* sb = reinterpret_cast<const float4*>(&Bmat[(size_t)(gn+lr)*H_ + k0 + lk]);
        #pragma unroll
        for (int i = 0; i < 4; ++i) {
            float4 va = sa[i];
            int kk = lk + i * 4;
            As[kk+0][lr] = va.x; As[kk+1][lr] = va.y; As[kk+2][lr] = va.z; As[kk+3][lr] = va.w;
            float4 vb = sb[i];
            Bs[kk+0][lr] = vb.x; Bs[kk+1][lr] = vb.y; Bs[kk+2][lr] = vb.z; Bs[kk+3][lr] = vb.w;
        }
        __syncthreads();
        #pragma unroll 8
        for (int k = 0; k < PBK; ++k) {
            float av[8], bv[8];
            *reinterpret_cast<float4*>(&av[0]) = *reinterpret_cast<const float4*>(&As[k][m0]);
            *reinterpret_cast<float4*>(&av[4]) = *reinterpret_cast<const float4*>(&As[k][m0+4]);
            *reinterpret_cast<float4*>(&bv[0]) = *reinterpret_cast<const float4*>(&Bs[k][n0]);
            *reinterpret_cast<float4*>(&bv[4]) = *reinterpret_cast<const float4*>(&Bs[k][n0+4]);
            #pragma unroll
            for (int mi = 0; mi < 8; ++mi)
                #pragma unroll
                for (int ni = 0; ni < 8; ++ni)
                    acc[mi][ni] = fmaf(av[mi], bv[ni], acc[mi][ni]);
        }
        __syncthreads();
    }
    // epilogue: exp (no max subtraction needed: |logit| << 88), row-sum, store
    #pragma unroll
    for (int mi = 0; mi < 8; ++mi) {
        int row = gm + m0 + mi;
        float p[8]; float s = 0.f;
        #pragma unroll
        for (int ni = 0; ni < 8; ++ni) { p[ni] = __expf(acc[mi][ni]); s += p[ni]; }
        #pragma unroll
        for (int off = 8; off > 0; off >>= 1)
            s += __shfl_xor_sync(0xffffffffu, s, off);
        if (tx == 0) atomicAdd(&rowsum[row], s);
        float4* dst = reinterpret_cast<float4*>(&out[(size_t)row * V_ + gn + n0]);
        dst[0] = make_float4(p[0], p[1], p[2], p[3]);
        dst[1] = make_float4(p[4], p[5], p[6], p[7]);
    }
}

// rowsum -> masked reciprocal
__global__ void inv_kernel(const int* __restrict__ lengths, float* __restrict__ rs) {
    int i = blockIdx.x * 256 + threadIdx.x;
    if (i >= BT_) return;
    int b = i >> 7, t = i & (T_-1);
    float s = rs[i];
    rs[i] = (t < lengths[b]) ? (1.f / s) : 0.f;
}

// probs *= inv[row]   (vec4, exact grid)
__global__ void scale_kernel(float* __restrict__ out, const float* __restrict__ inv) {
    size_t i = (size_t)blockIdx.x * blockDim.x + threadIdx.x;  // vec4 index
    int row = (int)(i / (V_/4));
    float s = inv[row];
    float4 v = reinterpret_cast<float4*>(out)[i];
    v.x *= s; v.y *= s; v.z *= s; v.w *= s;
    reinterpret_cast<float4*>(out)[i] = v;
}

// ---------------- launcher ----------------
extern "C" void kernel_launch(void* const* d_in, const int* in_sizes, int n_in,
                              void* d_out, int out_size) {
    const int*   tokens  = (const int*)  d_in[0];
    const int*   lengths = (const int*)  d_in[1];
    const float* emb     = (const float*)d_in[2];
    const float* Wx1     = (const float*)d_in[3];
    const float* Wh1     = (const float*)d_in[4];
    const float* b1      = (const float*)d_in[5];
    const float* Wx2     = (const float*)d_in[6];
    const float* Wh2     = (const float*)d_in[7];
    const float* b2      = (const float*)d_in[8];
    float* out   = (float*)d_out;
    float* h2out = out + PROBS_;           // h2 written straight into output tail

    float *px, *ppre, *ph1, *pwxt, *pwht, *prs;
    cudaGetSymbolAddress((void**)&px,   g_x);
    cudaGetSymbolAddress((void**)&ppre, g_pre);
    cudaGetSymbolAddress((void**)&ph1,  g_h1);
    cudaGetSymbolAddress((void**)&pwxt, g_WxT);
    cudaGetSymbolAddress((void**)&pwht, g_WhT);
    cudaGetSymbolAddress((void**)&prs,  g_rowsum);

    dim3 tg(8, 8), tb(32, 32);

    zero_rowsum_kernel<<<16, 256>>>(prs);
    embed_kernel<<<BT_, H_>>>(tokens, lengths, emb, px);

    // layer 1
    transpose_kernel<<<tg, tb>>>(Wx1, pwxt);
    transpose_kernel<<<tg, tb>>>(Wh1, pwht);
    pre_gemm_kernel<<<BT_/16, 256>>>(px, pwxt, b1, ppre);
    rnn_kernel<<<B_, 256>>>(ppre, pwht, lengths, ph1);

    // layer 2
    transpose_kernel<<<tg, tb>>>(Wx2, pwxt);
    transpose_kernel<<<tg, tb>>>(Wh2, pwht);
    pre_gemm_kernel<<<BT_/16, 256>>>(ph1, pwxt, b2, ppre);
    rnn_kernel<<<B_, 256>>>(ppre, pwht, lengths, h2out);

    // tied projection + softmax
    proj_kernel<<<dim3(V_/PBN, BT_/PBM), 256>>>(h2out, emb, out, prs);
    inv_kernel<<<16, 256>>>(lengths, prs);
    scale_kernel<<<(unsigned)(PROBS_/4/256), 256>>>(out, prs);
}

// round 8
// speedup vs baseline: 1.4049x; 1.4049x over previous
#include <cuda_runtime.h>
#include <cuda_bf16.h>
#include <math.h>
#include <cstdint>

#define B_   32
#define T_   128
#define H_   256
#define V_   32000
#define BT_  (B_*T_)
#define KBIG 768
#define PROBS_ ((size_t)BT_ * V_)

// ---------------- device scratch (no allocation allowed) ----------------
__device__ float g_x[BT_*H_];
__device__ float g_pre[BT_*H_];
__device__ float g_h1[BT_*H_];
__device__ float g_WxT[H_*H_];
__device__ float g_WhT[H_*H_];
__device__ float g_rowsum[BT_];
__device__ __align__(16) __nv_bfloat16 g_Abig[(size_t)BT_ * KBIG];   // [h2_hi | h2_lo | h2_hi]
__device__ __align__(16) __nv_bfloat16 g_Bbig[(size_t)V_  * KBIG];   // [emb_hi | emb_hi | emb_lo]

// ---------------- PTX helpers (arch-portable only: sm_80+ features) ----------------
__device__ __forceinline__ uint32_t smem_u32(const void* p) {
    uint32_t a;
    asm("{ .reg .u64 t; cvta.to.shared.u64 t, %1; cvt.u32.u64 %0, t; }" : "=r"(a) : "l"(p));
    return a;
}
#define CP_ASYNC16(saddr, gptr) \
    asm volatile("cp.async.cg.shared.global [%0], [%1], 16;" :: "r"(saddr), "l"(gptr) : "memory")
#define CP_COMMIT() asm volatile("cp.async.commit_group;" ::: "memory")
#define CP_WAIT(n)  asm volatile("cp.async.wait_group %0;" :: "n"(n) : "memory")

__device__ __forceinline__ void ldsm_x4(uint32_t* r, uint32_t addr) {
    asm volatile("ldmatrix.sync.aligned.m8n8.x4.shared.b16 {%0,%1,%2,%3}, [%4];"
                 : "=r"(r[0]), "=r"(r[1]), "=r"(r[2]), "=r"(r[3]) : "r"(addr));
}
__device__ __forceinline__ void mma16816(float* c, const uint32_t* a, uint32_t b0, uint32_t b1) {
    asm volatile("mma.sync.aligned.m16n8k16.row.col.f32.bf16.bf16.f32 "
                 "{%0,%1,%2,%3}, {%4,%5,%6,%7}, {%8,%9}, {%0,%1,%2,%3};"
                 : "+f"(c[0]), "+f"(c[1]), "+f"(c[2]), "+f"(c[3])
                 : "r"(a[0]), "r"(a[1]), "r"(a[2]), "r"(a[3]), "r"(b0), "r"(b1));
}

// ---------------- small utility kernels ----------------
__global__ void zero_rowsum_kernel(float* rs) {
    int i = blockIdx.x * 256 + threadIdx.x;
    if (i < BT_) rs[i] = 0.f;
}

__global__ void embed_kernel(const int* __restrict__ tokens,
                             const int* __restrict__ lengths,
                             const float* __restrict__ emb,
                             float* __restrict__ x) {
    int i = blockIdx.x, j = threadIdx.x;
    int b = i >> 7, t = i & (T_-1);
    int tok = tokens[i];
    float v = (t < lengths[b]) ? emb[(size_t)tok * H_ + j] : 0.f;
    x[(size_t)i * H_ + j] = v;
}

__global__ void transpose_kernel(const float* __restrict__ src, float* __restrict__ dst) {
    __shared__ float tile[32][33];
    int x = blockIdx.x * 32 + threadIdx.x;
    int y = blockIdx.y * 32 + threadIdx.y;
    tile[threadIdx.y][threadIdx.x] = src[y * H_ + x];
    __syncthreads();
    x = blockIdx.y * 32 + threadIdx.x;
    y = blockIdx.x * 32 + threadIdx.y;
    dst[y * H_ + x] = tile[threadIdx.x][threadIdx.y];
}

// split fp32 -> 3-term bf16 layout. mode 0: A-style [hi|lo|hi]; mode 1: B-style [hi|hi|lo]
__global__ void split_kernel(const float* __restrict__ src, __nv_bfloat16* __restrict__ dst,
                             int rows, int mode) {
    int i = blockIdx.x * 256 + threadIdx.x;
    if (i >= rows * H_) return;
    int r = i >> 8, c = i & 255;
    float a = src[i];
    __nv_bfloat16 hi = __float2bfloat16(a);
    __nv_bfloat16 lo = __float2bfloat16(a - __bfloat162float(hi));
    __nv_bfloat16* d = dst + (size_t)r * KBIG + c;
    if (mode == 0) { d[0] = hi; d[256] = lo; d[512] = hi; }
    else           { d[0] = hi; d[256] = hi; d[512] = lo; }
}

// ---------------- pre-activation GEMM (unchanged) ----------------
__global__ __launch_bounds__(256)
void pre_gemm_kernel(const float* __restrict__ X, const float* __restrict__ WT,
                     const float* __restrict__ bias, float* __restrict__ out) {
    __shared__ float Xs[H_][16];
    const int r0 = blockIdx.x * 16;
    const int tid = threadIdx.x;
    {
        int m  = tid >> 4;
        int kq = (tid & 15) * 16;
        const float4* src = reinterpret_cast<const float4*>(&X[(size_t)(r0+m)*H_ + kq]);
        #pragma unroll
        for (int i = 0; i < 4; ++i) {
            float4 v = src[i];
            int k = kq + i * 4;
            Xs[k+0][m] = v.x; Xs[k+1][m] = v.y; Xs[k+2][m] = v.z; Xs[k+3][m] = v.w;
        }
    }
    __syncthreads();
    const int j = tid;
    float bb = bias[j];
    float acc[16];
    #pragma unroll
    for (int m = 0; m < 16; ++m) acc[m] = bb;
    #pragma unroll 8
    for (int k = 0; k < H_; ++k) {
        float w = WT[k * H_ + j];
        #pragma unroll
        for (int m0 = 0; m0 < 16; m0 += 4) {
            float4 xv = *reinterpret_cast<const float4*>(&Xs[k][m0]);
            acc[m0+0] = fmaf(w, xv.x, acc[m0+0]);
            acc[m0+1] = fmaf(w, xv.y, acc[m0+1]);
            acc[m0+2] = fmaf(w, xv.z, acc[m0+2]);
            acc[m0+3] = fmaf(w, xv.w, acc[m0+3]);
        }
    }
    #pragma unroll
    for (int m = 0; m < 16; ++m) out[(size_t)(r0+m)*H_ + j] = acc[m];
}

// ---------------- recurrence (unchanged) ----------------
__global__ __launch_bounds__(256)
void rnn_kernel(const float* __restrict__ pre, const float* __restrict__ WhT,
                const int* __restrict__ lengths, float* __restrict__ hout) {
    __shared__ float hs[H_];
    __shared__ float red[3][H_];
    const int b   = blockIdx.x;
    const int tid = threadIdx.x;
    const int jj  = (tid & 63) * 4;
    const int kk  = tid >> 6;
    const int k0  = kk * 64;
    hs[tid] = 0.f;
    __syncthreads();
    const int len = lengths[b];
    const float* preb = pre  + (size_t)b * T_ * H_;
    float*      houtb = hout + (size_t)b * T_ * H_;

    for (int t = 0; t < T_; ++t) {
        float a0 = 0.f, a1 = 0.f, a2 = 0.f, a3 = 0.f;
        const float* wp = WhT + (size_t)k0 * H_ + jj;
        #pragma unroll 16
        for (int k = 0; k < 64; ++k) {
            float h = hs[k0 + k];
            float4 w = *reinterpret_cast<const float4*>(wp);
            wp += H_;
            a0 = fmaf(w.x, h, a0); a1 = fmaf(w.y, h, a1);
            a2 = fmaf(w.z, h, a2); a3 = fmaf(w.w, h, a3);
        }
        if (kk > 0)
            *reinterpret_cast<float4*>(&red[kk-1][jj]) = make_float4(a0, a1, a2, a3);
        __syncthreads();
        if (kk == 0) {
            #pragma unroll
            for (int r = 0; r < 3; ++r) {
                float4 rv = *reinterpret_cast<const float4*>(&red[r][jj]);
                a0 += rv.x; a1 += rv.y; a2 += rv.z; a3 += rv.w;
            }
            float4 p = *reinterpret_cast<const float4*>(&preb[t * H_ + jj]);
            float h0 = tanhf(a0 + p.x), h1 = tanhf(a1 + p.y);
            float h2 = tanhf(a2 + p.z), h3 = tanhf(a3 + p.w);
            hs[jj+0] = h0; hs[jj+1] = h1; hs[jj+2] = h2; hs[jj+3] = h3;
            float m = (t < len) ? 1.f : 0.f;
            *reinterpret_cast<float4*>(&houtb[t * H_ + jj]) =
                make_float4(h0*m, h1*m, h2*m, h3*m);
        }
        __syncthreads();
    }
}

// ---------------- HMMA projection: [4096,768]bf16 x [32000,768]bf16^T -> exp -> probs ----
// CTA tile 128x128, K chunks of 64, double-buffered cp.async, 8 warps of 32x64.
#define PBM 128
#define PBN 128
#define PBK 64
#define NCHUNK (KBIG / PBK)          // 12
#define RS  72                        // smem row stride in bf16 (144 B; 9x16B -> conflict-free)
#define RSB (RS * 2)                  // bytes
#define BUFB (PBM * RSB)              // 18432 B per tile buffer
#define PROJ_SMEM (4 * BUFB)          // A0 B0 A1 B1 = 73728 B

__global__ __launch_bounds__(256, 2)
void proj_mma_kernel(const __nv_bfloat16* __restrict__ Abig,
                     const __nv_bfloat16* __restrict__ Bbig,
                     float* __restrict__ out,
                     float* __restrict__ rowsum) {
    extern __shared__ char smem[];
    const uint32_t sb = smem_u32(smem);
    const int tid = threadIdx.x;
    const int wid = tid >> 5;
    const int l   = tid & 31;
    const int gn  = blockIdx.x * PBN;
    const int gm  = blockIdx.y * PBM;
    const int wm  = (wid & 3) * 32;      // warp M offset in tile
    const int wn  = (wid >> 2) * 64;     // warp N offset in tile

    // buffer bases: [A0][B0][A1][B1]
    const uint32_t aB[2] = { sb,            sb + 2*BUFB };
    const uint32_t bB[2] = { sb + BUFB,     sb + 3*BUFB };

    // per-thread load slots: 4 x 16B for A, 4 x 16B for B per chunk
    const int lrow = tid >> 3;           // 0..31 base row (x4 via +32 stride... no: idx scheme)
    const int lseg = tid & 7;            // 16B segment 0..7

    float acc[2][8][4];
    #pragma unroll
    for (int mt = 0; mt < 2; ++mt)
        #pragma unroll
        for (int nt = 0; nt < 8; ++nt)
            #pragma unroll
            for (int q = 0; q < 4; ++q) acc[mt][nt][q] = 0.f;

    auto load_chunk = [&](int c) {
        const int buf = c & 1;
        const size_t kofs = (size_t)c * PBK + lseg * 8;
        #pragma unroll
        for (int i = 0; i < 4; ++i) {
            int r = lrow + i * 32;
            CP_ASYNC16(aB[buf] + r * RSB + lseg * 16,
                       &Abig[(size_t)(gm + r) * KBIG + kofs]);
        }
        #pragma unroll
        for (int i = 0; i < 4; ++i) {
            int r = lrow + i * 32;
            CP_ASYNC16(bB[buf] + r * RSB + lseg * 16,
                       &Bbig[(size_t)(gn + r) * KBIG + kofs]);
        }
        CP_COMMIT();
    };

    // ldmatrix lane address components
    const int a_row_in16 = (l & 7) + (l & 8);       // 0..15
    const int a_kh       = (l >> 4) & 1;            // k-half
    const int b_row_in16 = (l & 7) + ((l & 16) >> 1);  // 0..7 then 8..15
    const int b_kh       = (l >> 3) & 1;

    load_chunk(0);

    for (int c = 0; c < NCHUNK; ++c) {
        const int buf = c & 1;
        if (c + 1 < NCHUNK) { load_chunk(c + 1); CP_WAIT(1); }
        else                { CP_WAIT(0); }
        __syncthreads();

        #pragma unroll
        for (int ks = 0; ks < 4; ++ks) {
            uint32_t afr[2][4];
            #pragma unroll
            for (int mt = 0; mt < 2; ++mt) {
                uint32_t addr = aB[buf] + (wm + mt*16 + a_row_in16) * RSB
                              + (ks * 2 + a_kh) * 16;
                ldsm_x4(afr[mt], addr);
            }
            #pragma unroll
            for (int nt2 = 0; nt2 < 4; ++nt2) {
                uint32_t bfr[4];
                uint32_t addr = bB[buf] + (wn + nt2*16 + b_row_in16) * RSB
                              + (ks * 2 + b_kh) * 16;
                ldsm_x4(bfr, addr);
                #pragma unroll
                for (int mt = 0; mt < 2; ++mt) {
                    mma16816(acc[mt][nt2*2+0], afr[mt], bfr[0], bfr[1]);
                    mma16816(acc[mt][nt2*2+1], afr[mt], bfr[2], bfr[3]);
                }
            }
        }
        __syncthreads();
    }

    // epilogue: exp + rowsum + store. c0,c1 -> (row, col..col+1); c2,c3 -> (row+8, ...)
    const int r4 = l >> 2;
    const int cl = (l & 3) * 2;
    float s[2][2] = {{0.f,0.f},{0.f,0.f}};
    #pragma unroll
    for (int mt = 0; mt < 2; ++mt) {
        const int row0 = gm + wm + mt*16 + r4;
        #pragma unroll
        for (int nt = 0; nt < 8; ++nt) {
            const int col = gn + wn + nt*8 + cl;
            float v0 = __expf(acc[mt][nt][0]);
            float v1 = __expf(acc[mt][nt][1]);
            float v2 = __expf(acc[mt][nt][2]);
            float v3 = __expf(acc[mt][nt][3]);
            s[mt][0] += v0 + v1;
            s[mt][1] += v2 + v3;
            *reinterpret_cast<float2*>(&out[(size_t)row0       * V_ + col]) = make_float2(v0, v1);
            *reinterpret_cast<float2*>(&out[(size_t)(row0 + 8) * V_ + col]) = make_float2(v2, v3);
        }
    }
    #pragma unroll
    for (int mt = 0; mt < 2; ++mt)
        #pragma unroll
        for (int h = 0; h < 2; ++h) {
            float v = s[mt][h];
            v += __shfl_xor_sync(0xffffffffu, v, 1);
            v += __shfl_xor_sync(0xffffffffu, v, 2);
            if ((l & 3) == 0)
                atomicAdd(&rowsum[gm + wm + mt*16 + h*8 + r4], v);
        }
}

// rowsum -> masked reciprocal
__global__ void inv_kernel(const int* __restrict__ lengths, float* __restrict__ rs) {
    int i = blockIdx.x * 256 + threadIdx.x;
    if (i >= BT_) return;
    int b = i >> 7, t = i & (T_-1);
    float s = rs[i];
    rs[i] = (t < lengths[b]) ? (1.f / s) : 0.f;
}

__global__ void scale_kernel(float* __restrict__ out, const float* __restrict__ inv) {
    size_t i = (size_t)blockIdx.x * blockDim.x + threadIdx.x;
    int row = (int)(i / (V_/4));
    float s = inv[row];
    float4 v = reinterpret_cast<float4*>(out)[i];
    v.x *= s; v.y *= s; v.z *= s; v.w *= s;
    reinterpret_cast<float4*>(out)[i] = v;
}

// ---------------- launcher ----------------
extern "C" void kernel_launch(void* const* d_in, const int* in_sizes, int n_in,
                              void* d_out, int out_size) {
    const int*   tokens  = (const int*)  d_in[0];
    const int*   lengths = (const int*)  d_in[1];
    const float* emb     = (const float*)d_in[2];
    const float* Wx1     = (const float*)d_in[3];
    const float* Wh1     = (const float*)d_in[4];
    const float* b1      = (const float*)d_in[5];
    const float* Wx2     = (const float*)d_in[6];
    const float* Wh2     = (const float*)d_in[7];
    const float* b2      = (const float*)d_in[8];
    float* out   = (float*)d_out;
    float* h2out = out + PROBS_;

    float *px, *ppre, *ph1, *pwxt, *pwht, *prs;
    __nv_bfloat16 *pA, *pB;
    cudaGetSymbolAddress((void**)&px,   g_x);
    cudaGetSymbolAddress((void**)&ppre, g_pre);
    cudaGetSymbolAddress((void**)&ph1,  g_h1);
    cudaGetSymbolAddress((void**)&pwxt, g_WxT);
    cudaGetSymbolAddress((void**)&pwht, g_WhT);
    cudaGetSymbolAddress((void**)&prs,  g_rowsum);
    cudaGetSymbolAddress((void**)&pA,   g_Abig);
    cudaGetSymbolAddress((void**)&pB,   g_Bbig);

    cudaFuncSetAttribute(proj_mma_kernel,
                         cudaFuncAttributeMaxDynamicSharedMemorySize, PROJ_SMEM);

    dim3 tg(8, 8), tb(32, 32);

    zero_rowsum_kernel<<<16, 256>>>(prs);
    embed_kernel<<<BT_, H_>>>(tokens, lengths, emb, px);
    // B-side split of emb is independent of everything else: launch early
    split_kernel<<<(V_ * H_ + 255) / 256, 256>>>(emb, pB, V_, 1);

    // layer 1
    transpose_kernel<<<tg, tb>>>(Wx1, pwxt);
    transpose_kernel<<<tg, tb>>>(Wh1, pwht);
    pre_gemm_kernel<<<BT_/16, 256>>>(px, pwxt, b1, ppre);
    rnn_kernel<<<B_, 256>>>(ppre, pwht, lengths, ph1);

    // layer 2
    transpose_kernel<<<tg, tb>>>(Wx2, pwxt);
    transpose_kernel<<<tg, tb>>>(Wh2, pwht);
    pre_gemm_kernel<<<BT_/16, 256>>>(ph1, pwxt, b2, ppre);
    rnn_kernel<<<B_, 256>>>(ppre, pwht, lengths, h2out);

    // A-side split of h2
    split_kernel<<<(BT_ * H_ + 255) / 256, 256>>>(h2out, pA, BT_, 0);

    // HMMA projection + softmax
    proj_mma_kernel<<<dim3(V_/PBN, BT_/PBM), 256, PROJ_SMEM>>>(pA, pB, out, prs);
    inv_kernel<<<16, 256>>>(lengths, prs);
    scale_kernel<<<(unsigned)(PROBS_/4/256), 256>>>(out, prs);
}